// round 2
// baseline (speedup 1.0000x reference)
#include <cuda_runtime.h>
#include <math.h>

#define BB  256      // batch
#define HH  256      // hidden
#define NLY 6        // layers
#define SS  128      // steps
#define K0  128      // CIN*WIN
#define G3  768      // 3*H

struct Ptrs {
  const float *x, *Wih0, *Wih, *Whh, *bih, *bhh, *h0;
  const float *aW1, *aW2, *aW3, *aW4;
  const float *sdW1,*sdb1,*sdW2,*sdb2,*sdW3,*sdb3,*sdW4,*sdb4;
  const float *odW1,*odb1,*odW2,*odb2,*odW3,*odb3,*odW4,*odb4;
  float* out;
};

// scratch (device globals -- no allocation allowed)
__device__ __align__(16) float g_h[2][NLY][BB][HH];
__device__ __align__(16) float g_hpre[NLY][BB][HH];
__device__ __align__(16) float g_sh[NLY][BB][HH];
__device__ __align__(16) float g_Gi[NLY][BB][G3];
__device__ __align__(16) float g_Gh[NLY][BB][G3];
__device__ __align__(16) float g_A1[NLY][BB][512];
__device__ __align__(16) float g_A2[NLY][BB][512];
__device__ __align__(16) float g_A3[NLY][BB][512];
__device__ __align__(16) float g_W2p[NLY][128][128];
__device__ __align__(16) float g_W3p[NLY][128][128];

#define YSEQ_OFF 8388608ul
#define YONE_OFF 9437184ul

typedef unsigned long long u64;

__device__ __forceinline__ u64 dup2(float a) {
  u64 d; unsigned ai = __float_as_uint(a);
  asm("mov.b64 %0, {%1, %1};" : "=l"(d) : "r"(ai));
  return d;
}
__device__ __forceinline__ void fma2(u64& acc, u64 a, u64 b) {
  asm("fma.rn.f32x2 %0, %1, %2, %0;" : "+l"(acc) : "l"(a), "l"(b));
}
__device__ __forceinline__ void unpack2(u64 v, float& lo, float& hi) {
  unsigned l_, h_;
  asm("mov.b64 {%0, %1}, %2;" : "=r"(l_), "=r"(h_) : "l"(v));
  lo = __uint_as_float(l_); hi = __uint_as_float(h_);
}

// ---------------------------------------------------------------------------
// GEMM core: 64x64 output tile, 64 threads, 8x8 per thread via fma.rn.f32x2.
// acc[i][j] holds output cols (n0+tx*8+2j, +1) for row m0+ty*8+i.
// A: caller pre-offset to m0, row stride lda (lda=0 => broadcast row).
// Optional col gather for SortAttn shuffle: col(k) = (k>>5)*128 + gbase + (k&31).
// Bw: caller pre-offset to n0, row-major, stride ldb.
// ---------------------------------------------------------------------------
__device__ __forceinline__ void gemm64(
    const float* __restrict__ A, int lda,
    const float* __restrict__ Bw, int ldb,
    int K, int gather, int gbase,
    u64 acc[8][4], float* As, float* Bs)
{
  const int t = threadIdx.x;       // 0..63
  const int nb = K >> 4;
  float4 ra[4], rb[4];

  auto loadT = [&](int kb) {
    int k0 = kb << 4;
    const float* pa;
    if (gather) pa = A + (size_t)t * lda + (((k0 >> 5) << 7) + gbase + (k0 & 31));
    else        pa = A + (size_t)t * lda + k0;
    ra[0] = *(const float4*)(pa);     ra[1] = *(const float4*)(pa + 4);
    ra[2] = *(const float4*)(pa + 8); ra[3] = *(const float4*)(pa + 12);
    const float* pb = Bw + (size_t)t * ldb + k0;
    rb[0] = *(const float4*)(pb);     rb[1] = *(const float4*)(pb + 4);
    rb[2] = *(const float4*)(pb + 8); rb[3] = *(const float4*)(pb + 12);
  };
  auto storeT = [&](int buf) {
    float* as = As + buf * 1024;
    float* bs = Bs + buf * 1024;
#pragma unroll
    for (int q = 0; q < 4; q++) {
      as[(q*4+0)*64 + t] = ra[q].x; as[(q*4+1)*64 + t] = ra[q].y;
      as[(q*4+2)*64 + t] = ra[q].z; as[(q*4+3)*64 + t] = ra[q].w;
      bs[(q*4+0)*64 + t] = rb[q].x; bs[(q*4+1)*64 + t] = rb[q].y;
      bs[(q*4+2)*64 + t] = rb[q].z; bs[(q*4+3)*64 + t] = rb[q].w;
    }
  };
  const int tx = t & 7, ty = t >> 3;
  auto compute = [&](int buf) {
    const float* as = As + buf * 1024 + ty * 8;
    const float* bs = Bs + buf * 1024 + tx * 8;
#pragma unroll
    for (int kk = 0; kk < 16; kk++) {
      float4 a0 = *(const float4*)(as + kk*64);
      float4 a1 = *(const float4*)(as + kk*64 + 4);
      ulonglong2 b0 = *(const ulonglong2*)(bs + kk*64);
      ulonglong2 b1 = *(const ulonglong2*)(bs + kk*64 + 4);
      u64 bp[4] = {b0.x, b0.y, b1.x, b1.y};
      float av[8] = {a0.x, a0.y, a0.z, a0.w, a1.x, a1.y, a1.z, a1.w};
#pragma unroll
      for (int i = 0; i < 8; i++) {
        u64 ad = dup2(av[i]);
#pragma unroll
        for (int j = 0; j < 4; j++) fma2(acc[i][j], ad, bp[j]);
      }
    }
  };

  loadT(0); storeT(0); __syncthreads();
  for (int kb = 1; kb < nb; kb++) {
    loadT(kb);
    compute((kb - 1) & 1);
    storeT(kb & 1);
    __syncthreads();
  }
  compute((nb - 1) & 1);
}

// ---------------------------------------------------------------------------
// prep: permute aW2/aW3 so shuffled-activation GEMM reads contiguously.
// ---------------------------------------------------------------------------
__global__ void prep_kernel(Ptrs P) {
  int i = blockIdx.x * blockDim.x + threadIdx.x;
  const int total = NLY * 128 * 128;
  if (i < total) {
    int l = i >> 14; int r = i & 16383; int j = r >> 7; int m = r & 127;
    int src = l * 16384 + j * 128 + ((m & 31) << 2) + (m >> 5);
    g_W2p[l][j][m] = P.aW2[src];
    g_W3p[l][j][m] = P.aW3[src];
  }
}

// ---------------------------------------------------------------------------
// Stage 1: Gi = inp @ Wih^T ; Gh = h_prev @ Whh^T   grid(48, nA, 2), 64 thr
// ---------------------------------------------------------------------------
__global__ void gru_gemm_kernel(Ptrs P, int w, int lmin, int pp) {
  __shared__ float As[2048], Bs[2048];
  int l = lmin + blockIdx.y, t = w - l;
  int m0 = (blockIdx.x & 3) << 6;
  int n0 = (blockIdx.x >> 2) << 6;
  const float *A, *W; int lda, K; float* out;
  if (blockIdx.z == 0) {
    if (l == 0) { A = P.x + (size_t)t * K0 + (size_t)m0 * 16384; lda = 16384; K = K0;
                  W = P.Wih0 + (size_t)n0 * K0; }
    else        { A = &g_h[pp][l-1][m0][0]; lda = HH; K = HH;
                  W = P.Wih + ((size_t)(l-1) * G3 + n0) * HH; }
    out = &g_Gi[l][0][0];
  } else {
    if (t == 0) { A = P.h0 + l * HH; lda = 0; }
    else        { A = &g_h[pp][l][m0][0]; lda = HH; }
    K = HH; W = P.Whh + ((size_t)l * G3 + n0) * HH;
    out = &g_Gh[l][0][0];
  }
  u64 acc[8][4] = {};
  gemm64(A, lda, W, K, K, 0, 0, acc, As, Bs);
  int tx = threadIdx.x & 7, ty = threadIdx.x >> 3;
#pragma unroll
  for (int i = 0; i < 8; i++) {
    int m = m0 + ty*8 + i;
#pragma unroll
    for (int j = 0; j < 4; j++) {
      float lo, hi; unpack2(acc[i][j], lo, hi);
      *(float2*)(out + (size_t)m * G3 + n0 + tx*8 + 2*j) = make_float2(lo, hi);
    }
  }
}

// ---------------------------------------------------------------------------
// Stage 2+3 fused: GRU gates -> hpre, then warp-synchronous bitonic sort.
// One warp per batch row. grid(32, nA), 256 threads (8 warps = 8 rows).
// ---------------------------------------------------------------------------
__global__ void gatesort_kernel(Ptrs P, int w, int lmin, int pp) {
  int l = lmin + blockIdx.y, t = w - l;
  int warp = threadIdx.x >> 5, lane = threadIdx.x & 31;
  int b = blockIdx.x * 8 + warp;
  __shared__ float v[8][256];
  const float* bi = P.bih + l * G3;
  const float* bh = P.bhh + l * G3;
#pragma unroll
  for (int q = 0; q < 8; q++) {
    int j = lane + (q << 5);
    float gi0 = g_Gi[l][b][j]      + bi[j];
    float gi1 = g_Gi[l][b][j+256]  + bi[j+256];
    float gi2 = g_Gi[l][b][j+512]  + bi[j+512];
    float gh0 = g_Gh[l][b][j]      + bh[j];
    float gh1 = g_Gh[l][b][j+256]  + bh[j+256];
    float gh2 = g_Gh[l][b][j+512]  + bh[j+512];
    float r = 1.f / (1.f + expf(-(gi0 + gh0)));
    float z = 1.f / (1.f + expf(-(gi1 + gh1)));
    float n = tanhf(gi2 + r * gh2);
    float hp = (t == 0) ? P.h0[l * HH + j] : g_h[pp][l][b][j];
    float hv = (1.f - z) * n + z * hp;
    g_hpre[l][b][j] = hv;
    v[warp][j] = hv;
  }
  __syncwarp();
  for (int k = 2; k <= 256; k <<= 1) {
    for (int jj = k >> 1; jj > 0; jj >>= 1) {
#pragma unroll
      for (int q = 0; q < 8; q++) {
        int idx = lane + (q << 5);
        int ixj = idx ^ jj;
        if (ixj > idx) {
          float a = v[warp][idx], c = v[warp][ixj];
          bool up = ((idx & k) == 0);
          if ((a > c) == up) { v[warp][idx] = c; v[warp][ixj] = a; }
        }
      }
      __syncwarp();
    }
  }
#pragma unroll
  for (int q = 0; q < 8; q++) {
    int j = lane + (q << 5);
    g_sh[l][b][j] = v[warp][j];
  }
}

// ---------------------------------------------------------------------------
// Stage 4: A1 = [hpre | sorted] @ W1^T   grid(32, nA), 64 thr
// ---------------------------------------------------------------------------
__global__ void a1_kernel(Ptrs P, int lmin) {
  __shared__ float As[2048], Bs[2048];
  int l = lmin + blockIdx.y;
  int m0 = (blockIdx.x & 3) << 6;
  int n0 = (blockIdx.x >> 2) << 6;
  const float* A = (n0 < 256) ? &g_hpre[l][m0][0] : &g_sh[l][m0][0];
  const float* W = P.aW1 + ((size_t)l * 256 + (n0 & 255)) * 256;
  u64 acc[8][4] = {};
  gemm64(A, HH, W, 256, 256, 0, 0, acc, As, Bs);
  int tx = threadIdx.x & 7, ty = threadIdx.x >> 3;
  float* out = &g_A1[l][0][0];
#pragma unroll
  for (int i = 0; i < 8; i++) {
    int m = m0 + ty*8 + i;
#pragma unroll
    for (int j = 0; j < 4; j++) {
      float lo, hi; unpack2(acc[i][j], lo, hi);
      *(float2*)(out + (size_t)m * 512 + n0 + tx*8 + 2*j) = make_float2(lo, hi);
    }
  }
}

// ---------------------------------------------------------------------------
// Stage 5/6: A2 = shuffle(A1)@W2p^T ; A3 = relu(shuffle(A2)@W3p^T)  grid(32,nA)
// ---------------------------------------------------------------------------
__global__ void a23_kernel(Ptrs P, int lmin, int which) {
  __shared__ float As[2048], Bs[2048];
  int l = lmin + blockIdx.y;
  int m0 = (blockIdx.x & 3) << 6;
  int f0 = (blockIdx.x >> 2) << 6;
  int grp = f0 >> 7, j0 = f0 & 127;
  const float* A = (which == 2) ? &g_A1[l][m0][0] : &g_A2[l][m0][0];
  const float* W = (which == 2) ? &g_W2p[l][j0][0] : &g_W3p[l][j0][0];
  float* out     = (which == 2) ? &g_A2[l][0][0]  : &g_A3[l][0][0];
  u64 acc[8][4] = {};
  gemm64(A, 512, W, 128, 128, 1, grp * 32, acc, As, Bs);
  int tx = threadIdx.x & 7, ty = threadIdx.x >> 3;
#pragma unroll
  for (int i = 0; i < 8; i++) {
    int m = m0 + ty*8 + i;
#pragma unroll
    for (int j = 0; j < 4; j++) {
      float lo, hi; unpack2(acc[i][j], lo, hi);
      if (which == 3) { lo = fmaxf(lo, 0.f); hi = fmaxf(hi, 0.f); }
      *(float2*)(out + (size_t)m * 512 + f0 + tx*8 + 2*j) = make_float2(lo, hi);
    }
  }
}

// ---------------------------------------------------------------------------
// Stage 7: a4 = A3 @ W4^T ; h = hpre * sigmoid(a4)   grid(16, nA), 64 thr
// ---------------------------------------------------------------------------
__global__ void a4_kernel(Ptrs P, int w, int lmin, int p) {
  __shared__ float As[2048], Bs[2048];
  int l = lmin + blockIdx.y, t = w - l;
  int m0 = (blockIdx.x & 3) << 6;
  int n0 = (blockIdx.x >> 2) << 6;
  const float* A = &g_A3[l][m0][0];
  const float* W = P.aW4 + ((size_t)l * 256 + n0) * 512;
  u64 acc[8][4] = {};
  gemm64(A, 512, W, 512, 512, 0, 0, acc, As, Bs);
  int tx = threadIdx.x & 7, ty = threadIdx.x >> 3;
#pragma unroll
  for (int i = 0; i < 8; i++) {
    int m = m0 + ty*8 + i;
#pragma unroll
    for (int j = 0; j < 4; j++) {
      float lo, hi; unpack2(acc[i][j], lo, hi);
      int n = n0 + tx*8 + 2*j;
      float h0v = g_hpre[l][m][n]   * (1.f / (1.f + expf(-lo)));
      float h1v = g_hpre[l][m][n+1] * (1.f / (1.f + expf(-hi)));
      g_h[p][l][m][n]   = h0v;
      g_h[p][l][m][n+1] = h1v;
      if (l == NLY - 1) {
        P.out[(size_t)m * 32768 + (size_t)t * 256 + n]     = h0v;
        P.out[(size_t)m * 32768 + (size_t)t * 256 + n + 1] = h1v;
      }
    }
  }
}

// ---------------------------------------------------------------------------
// SeqDecoder: one thread per (b,s)
// ---------------------------------------------------------------------------
__global__ void seqdec_kernel(Ptrs P) {
  int idx = blockIdx.x * blockDim.x + threadIdx.x;
  int b = idx >> 7, s = idx & 127;
  const float* e = P.out + (size_t)b * 32768 + (size_t)s * 256;
  float a1[8][4], a2[8][4], a3[8][4];
#pragma unroll
  for (int g = 0; g < 8; g++)
#pragma unroll
    for (int o = 0; o < 4; o++) {
      float sum = P.sdb1[o];
#pragma unroll
      for (int m = 0; m < 32; m++) sum += e[g*32+m] * P.sdW1[o*32+m];
      a1[g][o] = sum;
    }
#pragma unroll
  for (int i = 0; i < 8; i++)
#pragma unroll
    for (int o = 0; o < 4; o++) {
      float sum = P.sdb2[o];
#pragma unroll
      for (int j = 0; j < 4; j++) {
        int f = i*4 + j;
        sum += a1[f & 7][f >> 3] * P.sdW2[o*4+j];
      }
      a2[i][o] = sum;
    }
#pragma unroll
  for (int i = 0; i < 8; i++)
#pragma unroll
    for (int o = 0; o < 4; o++) {
      float sum = P.sdb3[o];
#pragma unroll
      for (int j = 0; j < 4; j++) {
        int f = i*4 + j;
        sum += a2[f & 7][f >> 3] * P.sdW3[o*4+j];
      }
      a3[i][o] = sum;
    }
#pragma unroll
  for (int o = 0; o < 4; o++)
#pragma unroll
    for (int wv = 0; wv < 8; wv++) {
      float sum = P.sdb4[wv];
#pragma unroll
      for (int g = 0; g < 8; g++) {
        int f = o*8 + g;
        sum += a3[f >> 2][f & 3] * P.sdW4[wv*8+g];
      }
      P.out[YSEQ_OFF + (size_t)b * 4096 + (size_t)(s*8 + wv) * 4 + o] = sum;
    }
}

// ---------------------------------------------------------------------------
// OneDecoder: block per b; threads 0..9 handle s = 118..127, then mean
// ---------------------------------------------------------------------------
__global__ void onedec_kernel(Ptrs P) {
  int b = blockIdx.x;
  __shared__ float acc[10][4];
  int tid = threadIdx.x;
  if (tid < 10) {
    int s = 118 + tid;
    const float* e = P.out + (size_t)b * 32768 + (size_t)s * 256;
    float o1[8][4], o2[8][4], o3[8][4];
#pragma unroll
    for (int g = 0; g < 8; g++)
#pragma unroll
      for (int o = 0; o < 4; o++) {
        float sum = P.odb1[o];
#pragma unroll
        for (int m = 0; m < 32; m++) sum += e[g*32+m] * P.odW1[o*32+m];
        o1[g][o] = sum;
      }
#pragma unroll
    for (int i = 0; i < 8; i++)
#pragma unroll
      for (int o = 0; o < 4; o++) {
        float sum = P.odb2[o];
#pragma unroll
        for (int j = 0; j < 4; j++) {
          int f = i*4 + j;
          sum += o1[f & 7][f >> 3] * P.odW2[o*4+j];
        }
        o2[i][o] = sum;
      }
#pragma unroll
    for (int i = 0; i < 8; i++)
#pragma unroll
      for (int o = 0; o < 4; o++) {
        float sum = P.odb3[o];
#pragma unroll
        for (int j = 0; j < 4; j++) {
          int f = i*4 + j;
          sum += o2[f & 7][f >> 3] * P.odW3[o*4+j];
        }
        o3[i][o] = fmaxf(sum, 0.f);
      }
#pragma unroll
    for (int c = 0; c < 4; c++) {
      float sum = P.odb4[c];
#pragma unroll
      for (int f = 0; f < 32; f++) sum += o3[f >> 2][f & 3] * P.odW4[c*32+f];
      acc[tid][c] = 1.f / (1.f + expf(-sum));
    }
  }
  __syncthreads();
  if (tid < 4) {
    float s = 0.f;
#pragma unroll
    for (int i = 0; i < 10; i++) s += acc[i][tid];
    P.out[YONE_OFF + (size_t)b * 4 + tid] = s * 0.1f;
  }
}

// ---------------------------------------------------------------------------
extern "C" void kernel_launch(void* const* d_in, const int* in_sizes, int n_in,
                              void* d_out, int out_size) {
  (void)in_sizes; (void)n_in; (void)out_size;
  Ptrs P;
  P.x    = (const float*)d_in[0];
  P.Wih0 = (const float*)d_in[1];
  P.Wih  = (const float*)d_in[2];
  P.Whh  = (const float*)d_in[3];
  P.bih  = (const float*)d_in[4];
  P.bhh  = (const float*)d_in[5];
  P.h0   = (const float*)d_in[6];
  P.aW1  = (const float*)d_in[7];
  P.aW2  = (const float*)d_in[8];
  P.aW3  = (const float*)d_in[9];
  P.aW4  = (const float*)d_in[10];
  P.sdW1 = (const float*)d_in[11];
  P.sdb1 = (const float*)d_in[12];
  P.sdW2 = (const float*)d_in[13];
  P.sdb2 = (const float*)d_in[14];
  P.sdW3 = (const float*)d_in[15];
  P.sdb3 = (const float*)d_in[16];
  P.sdW4 = (const float*)d_in[17];
  P.sdb4 = (const float*)d_in[18];
  P.odW1 = (const float*)d_in[19];
  P.odb1 = (const float*)d_in[20];
  P.odW2 = (const float*)d_in[21];
  P.odb2 = (const float*)d_in[22];
  P.odW3 = (const float*)d_in[23];
  P.odb3 = (const float*)d_in[24];
  P.odW4 = (const float*)d_in[25];
  P.odb4 = (const float*)d_in[26];
  P.out  = (float*)d_out;

  prep_kernel<<<384, 256>>>(P);

  for (int w = 0; w < SS + NLY - 1; w++) {
    int lmin = w - (SS - 1); if (lmin < 0) lmin = 0;
    int lmax = (w < NLY - 1) ? w : NLY - 1;
    int nA = lmax - lmin + 1;
    int pp = (w + 1) & 1;
    int p  = w & 1;
    gru_gemm_kernel<<<dim3(48, nA, 2), 64>>>(P, w, lmin, pp);
    gatesort_kernel<<<dim3(32, nA), 256>>>(P, w, lmin, pp);
    a1_kernel<<<dim3(32, nA), 64>>>(P, lmin);
    a23_kernel<<<dim3(32, nA), 64>>>(P, lmin, 2);
    a23_kernel<<<dim3(32, nA), 64>>>(P, lmin, 3);
    a4_kernel<<<dim3(16, nA), 64>>>(P, w, lmin, p);
  }

  seqdec_kernel<<<128, 256>>>(P);
  onedec_kernel<<<256, 32>>>(P);
}

// round 3
// speedup vs baseline: 1.0249x; 1.0249x over previous
#include <cuda_runtime.h>
#include <math.h>

#define BB  256
#define HH  256
#define NLY 6
#define SS  128
#define K0  128
#define G3  768

struct Ptrs {
  const float *x, *Wih0, *Wih, *Whh, *bih, *bhh, *h0;
  const float *aW1, *aW2, *aW3, *aW4;
  const float *sdW1,*sdb1,*sdW2,*sdb2,*sdW3,*sdb3,*sdW4,*sdb4;
  const float *odW1,*odb1,*odW2,*odb2,*odW3,*odb3,*odW4,*odb4;
  float* out;
};

__device__ __align__(16) float g_h[2][NLY][BB][HH];
__device__ __align__(16) float g_hpre[NLY][BB][HH];
__device__ __align__(16) float g_sh[NLY][BB][HH];
__device__ __align__(16) float g_Gi[NLY][BB][G3];
__device__ __align__(16) float g_Gh[NLY][BB][G3];
__device__ __align__(16) float g_A1[NLY][BB][512];
__device__ __align__(16) float g_A2[NLY][BB][512];
__device__ __align__(16) float g_A3[NLY][BB][512];
__device__ __align__(16) float g_W2p[NLY][128][128];
__device__ __align__(16) float g_W3p[NLY][128][128];

#define YSEQ_OFF 8388608ul
#define YONE_OFF 9437184ul

typedef unsigned long long u64;

__device__ __forceinline__ u64 dup2(float a) {
  u64 d; unsigned ai = __float_as_uint(a);
  asm("mov.b64 %0, {%1, %1};" : "=l"(d) : "r"(ai));
  return d;
}
__device__ __forceinline__ void fma2(u64& acc, u64 a, u64 b) {
  asm("fma.rn.f32x2 %0, %1, %2, %0;" : "+l"(acc) : "l"(a), "l"(b));
}
__device__ __forceinline__ void unpack2(u64 v, float& lo, float& hi) {
  unsigned l_, h_;
  asm("mov.b64 {%0, %1}, %2;" : "=r"(l_), "=r"(h_) : "l"(v));
  lo = __uint_as_float(l_); hi = __uint_as_float(h_);
}

// ---------------------------------------------------------------------------
// GEMM core: 64 x TN output tile, 256 threads, TK=8, double-buffered.
// Thread tile: 4 rows x (TN/16) cols. Accumulators are M-paired f32x2:
// acc[p][j] covers rows (ty*4+2p, ty*4+2p+1), col n0+tx*(TN/16)+j.
// A operand read as natural u64 pair from transposed smem; B scalar dup'd.
// A: pre-offset to m0, stride lda (lda==0 -> broadcast single row).
// Optional gather on A cols (SortAttn shuffle): col(c)=(c>>5)*128+gbase+(c&31).
// Bw: weights [N,K] row-major, pre-offset to n0, stride ldb.
// ---------------------------------------------------------------------------
template<int TN>
__device__ __forceinline__ void gemm_core(
    const float* __restrict__ A, int lda,
    const float* __restrict__ Bw, int ldb,
    int K, int gather, int gbase,
    u64 acc[2][TN/16], float* As, float* Bs)
{
  constexpr int JN = TN / 16;
  const int t  = threadIdx.x;
  const int ar = t >> 2, ak = (t & 3) * 2;      // A loader: 64 rows x 8k, float2
  const int tx = t & 15, ty = t >> 4;
  int br, bo;
  if (TN == 128) { br = t >> 1; bo = (t & 1) * 4; }  // 128 rows x 8k, float4
  else           { br = t >> 2; bo = (t & 3) * 2; }  // 64 rows x 8k, float2

  float2 ra; float4 rb4; float2 rb2;

  auto loadT = [&](int k0) {
    int c = k0 + ak;
    int colA = gather ? (((c >> 5) << 7) + gbase + (c & 31)) : c;
    ra = *(const float2*)(A + (size_t)ar * lda + colA);
    if (TN == 128) rb4 = *(const float4*)(Bw + (size_t)br * ldb + k0 + bo);
    else           rb2 = *(const float2*)(Bw + (size_t)br * ldb + k0 + bo);
  };
  auto storeT = [&](int buf) {
    float* as = As + buf * 512;
    float* bs = Bs + buf * (8 * TN);
    as[(ak+0)*64 + ar] = ra.x;
    as[(ak+1)*64 + ar] = ra.y;
    if (TN == 128) {
      bs[(bo+0)*TN + br] = rb4.x; bs[(bo+1)*TN + br] = rb4.y;
      bs[(bo+2)*TN + br] = rb4.z; bs[(bo+3)*TN + br] = rb4.w;
    } else {
      bs[(bo+0)*TN + br] = rb2.x; bs[(bo+1)*TN + br] = rb2.y;
    }
  };
  auto compute = [&](int buf) {
    const float* as = As + buf * 512 + ty * 4;
    const float* bs = Bs + buf * (8 * TN) + tx * JN;
#pragma unroll
    for (int kk = 0; kk < 8; kk++) {
      ulonglong2 a2 = *(const ulonglong2*)(as + kk * 64);
      float bv[JN];
      if (TN == 128) {
        float4 b0 = *(const float4*)(bs + kk * TN);
        float4 b1 = *(const float4*)(bs + kk * TN + 4);
        bv[0]=b0.x; bv[1]=b0.y; bv[2]=b0.z; bv[3]=b0.w;
        bv[4]=b1.x; bv[5]=b1.y; bv[6]=b1.z; bv[7]=b1.w;
      } else {
        float4 b0 = *(const float4*)(bs + kk * TN);
        bv[0]=b0.x; bv[1]=b0.y; bv[2]=b0.z; bv[3]=b0.w;
      }
#pragma unroll
      for (int j = 0; j < JN; j++) {
        u64 bd = dup2(bv[j]);
        fma2(acc[0][j], a2.x, bd);
        fma2(acc[1][j], a2.y, bd);
      }
    }
  };

  const int nb = K >> 3;
  loadT(0); storeT(0); __syncthreads();
  for (int kb = 1; kb < nb; kb++) {
    loadT(kb << 3);
    compute((kb - 1) & 1);
    storeT(kb & 1);
    __syncthreads();
  }
  compute((nb - 1) & 1);
}

// Write the 4x(TN/16) thread tile: rows m0+ty*4+0..3, cols n0+tx*JN..
template<int TN>
__device__ __forceinline__ void get_rows(u64 acc[2][TN/16], float v[4][TN/16]) {
#pragma unroll
  for (int j = 0; j < TN/16; j++) {
    unpack2(acc[0][j], v[0][j], v[1][j]);
    unpack2(acc[1][j], v[2][j], v[3][j]);
  }
}

// ---------------------------------------------------------------------------
__global__ void prep_kernel(Ptrs P) {
  int i = blockIdx.x * blockDim.x + threadIdx.x;
  const int total = NLY * 128 * 128;
  if (i < total) {
    int l = i >> 14; int r = i & 16383; int j = r >> 7; int m = r & 127;
    int src = l * 16384 + j * 128 + ((m & 31) << 2) + (m >> 5);
    g_W2p[l][j][m] = P.aW2[src];
    g_W3p[l][j][m] = P.aW3[src];
  }
}

// ---------------------------------------------------------------------------
// Stage 1: Gi = inp @ Wih^T ; Gh = h_prev @ Whh^T.  grid(48, nA), 256 thr.
// blocks 0..23 -> Gi, 24..47 -> Gh;  within: m0=(j&3)*64, n0=(j>>2)*128.
// ---------------------------------------------------------------------------
__global__ void __launch_bounds__(256) gru_gemm_kernel(Ptrs P, int w, int lmin, int pp) {
  __shared__ __align__(16) float As[1024], Bs[2048];
  int l = lmin + blockIdx.y, t = w - l;
  int i = blockIdx.x;
  int which = (i >= 24); i -= which * 24;
  int m0 = (i & 3) << 6;
  int n0 = (i >> 2) << 7;
  const float *A, *W; int lda, K; float* out;
  if (!which) {
    if (l == 0) { A = P.x + (size_t)t * K0 + (size_t)m0 * 16384; lda = 16384; K = K0;
                  W = P.Wih0 + (size_t)n0 * K0; }
    else        { A = &g_h[pp][l-1][m0][0]; lda = HH; K = HH;
                  W = P.Wih + ((size_t)(l-1) * G3 + n0) * HH; }
    out = &g_Gi[l][0][0];
  } else {
    if (t == 0) { A = P.h0 + l * HH; lda = 0; }
    else        { A = &g_h[pp][l][m0][0]; lda = HH; }
    K = HH; W = P.Whh + ((size_t)l * G3 + n0) * HH;
    out = &g_Gh[l][0][0];
  }
  u64 acc[2][8] = {};
  gemm_core<128>(A, lda, W, K, K, 0, 0, acc, As, Bs);
  float v[4][8]; get_rows<128>(acc, v);
  int tx = threadIdx.x & 15, ty = threadIdx.x >> 4;
#pragma unroll
  for (int r = 0; r < 4; r++) {
    int m = m0 + ty*4 + r;
    float* po = out + (size_t)m * G3 + n0 + tx*8;
    *(float4*)(po)     = make_float4(v[r][0], v[r][1], v[r][2], v[r][3]);
    *(float4*)(po + 4) = make_float4(v[r][4], v[r][5], v[r][6], v[r][7]);
  }
}

// ---------------------------------------------------------------------------
// Stage 2+3 fused: gates -> hpre, then warp-synchronous bitonic sort.
// ---------------------------------------------------------------------------
__global__ void __launch_bounds__(256) gatesort_kernel(Ptrs P, int w, int lmin, int pp) {
  int l = lmin + blockIdx.y, t = w - l;
  int warp = threadIdx.x >> 5, lane = threadIdx.x & 31;
  int b = blockIdx.x * 8 + warp;
  __shared__ float v[8][256];
  const float* bi = P.bih + l * G3;
  const float* bh = P.bhh + l * G3;
#pragma unroll
  for (int q = 0; q < 8; q++) {
    int j = lane + (q << 5);
    float gi0 = g_Gi[l][b][j]      + bi[j];
    float gi1 = g_Gi[l][b][j+256]  + bi[j+256];
    float gi2 = g_Gi[l][b][j+512]  + bi[j+512];
    float gh0 = g_Gh[l][b][j]      + bh[j];
    float gh1 = g_Gh[l][b][j+256]  + bh[j+256];
    float gh2 = g_Gh[l][b][j+512]  + bh[j+512];
    float r = 1.f / (1.f + expf(-(gi0 + gh0)));
    float z = 1.f / (1.f + expf(-(gi1 + gh1)));
    float n = tanhf(gi2 + r * gh2);
    float hp = (t == 0) ? P.h0[l * HH + j] : g_h[pp][l][b][j];
    float hv = (1.f - z) * n + z * hp;
    g_hpre[l][b][j] = hv;
    v[warp][j] = hv;
  }
  __syncwarp();
  for (int k = 2; k <= 256; k <<= 1) {
    for (int jj = k >> 1; jj > 0; jj >>= 1) {
#pragma unroll
      for (int q = 0; q < 8; q++) {
        int idx = lane + (q << 5);
        int ixj = idx ^ jj;
        if (ixj > idx) {
          float a = v[warp][idx], c = v[warp][ixj];
          bool up = ((idx & k) == 0);
          if ((a > c) == up) { v[warp][idx] = c; v[warp][ixj] = a; }
        }
      }
      __syncwarp();
    }
  }
#pragma unroll
  for (int q = 0; q < 8; q++) {
    int j = lane + (q << 5);
    g_sh[l][b][j] = v[warp][j];
  }
}

// ---------------------------------------------------------------------------
// Stage 4: A1 = [hpre | sorted] @ W1^T.  grid(16, nA).
// ---------------------------------------------------------------------------
__global__ void __launch_bounds__(256) a1_kernel(Ptrs P, int lmin) {
  __shared__ __align__(16) float As[1024], Bs[2048];
  int l = lmin + blockIdx.y;
  int i = blockIdx.x;
  int m0 = (i & 3) << 6;
  int n0 = (i >> 2) << 7;
  const float* A = (n0 < 256) ? &g_hpre[l][m0][0] : &g_sh[l][m0][0];
  const float* W = P.aW1 + ((size_t)l * 256 + (n0 & 255)) * 256;
  u64 acc[2][8] = {};
  gemm_core<128>(A, HH, W, 256, 256, 0, 0, acc, As, Bs);
  float v[4][8]; get_rows<128>(acc, v);
  int tx = threadIdx.x & 15, ty = threadIdx.x >> 4;
  float* out = &g_A1[l][0][0];
#pragma unroll
  for (int r = 0; r < 4; r++) {
    int m = m0 + ty*4 + r;
    float* po = out + (size_t)m * 512 + n0 + tx*8;
    *(float4*)(po)     = make_float4(v[r][0], v[r][1], v[r][2], v[r][3]);
    *(float4*)(po + 4) = make_float4(v[r][4], v[r][5], v[r][6], v[r][7]);
  }
}

// ---------------------------------------------------------------------------
// Stage 5/6: A2 = shuffle(A1)@W2p^T ; A3 = relu(shuffle(A2)@W3p^T). grid(16,nA)
// ---------------------------------------------------------------------------
__global__ void __launch_bounds__(256) a23_kernel(Ptrs P, int lmin, int which) {
  __shared__ __align__(16) float As[1024], Bs[2048];
  int l = lmin + blockIdx.y;
  int i = blockIdx.x;
  int m0 = (i & 3) << 6;
  int f0 = (i >> 2) << 7;
  int grp = f0 >> 7, j0 = f0 & 127;
  const float* A = (which == 2) ? &g_A1[l][m0][0] : &g_A2[l][m0][0];
  const float* W = (which == 2) ? &g_W2p[l][j0][0] : &g_W3p[l][j0][0];
  float* out     = (which == 2) ? &g_A2[l][0][0]  : &g_A3[l][0][0];
  u64 acc[2][8] = {};
  gemm_core<128>(A, 512, W, 128, 128, 1, grp * 32, acc, As, Bs);
  float v[4][8]; get_rows<128>(acc, v);
  int tx = threadIdx.x & 15, ty = threadIdx.x >> 4;
#pragma unroll
  for (int r = 0; r < 4; r++) {
    int m = m0 + ty*4 + r;
#pragma unroll
    for (int j = 0; j < 8 && which == 3; j++) v[r][j] = fmaxf(v[r][j], 0.f);
    float* po = out + (size_t)m * 512 + f0 + tx*8;
    *(float4*)(po)     = make_float4(v[r][0], v[r][1], v[r][2], v[r][3]);
    *(float4*)(po + 4) = make_float4(v[r][4], v[r][5], v[r][6], v[r][7]);
  }
}

// ---------------------------------------------------------------------------
// Stage 7: a4 = A3 @ W4^T ; h = hpre * sigmoid(a4).  grid(16, nA), TN=64.
// ---------------------------------------------------------------------------
__global__ void __launch_bounds__(256) a4_kernel(Ptrs P, int w, int lmin, int p) {
  __shared__ __align__(16) float As[1024], Bs[1024];
  int l = lmin + blockIdx.y, t = w - l;
  int i = blockIdx.x;
  int m0 = (i & 3) << 6;
  int n0 = (i >> 2) << 6;        // 4 tiles of 64 = 256
  const float* A = &g_A3[l][m0][0];
  const float* W = P.aW4 + ((size_t)l * 256 + n0) * 512;
  u64 acc[2][4] = {};
  gemm_core<64>(A, 512, W, 512, 512, 0, 0, acc, As, Bs);
  float v[4][4]; get_rows<64>(acc, v);
  int tx = threadIdx.x & 15, ty = threadIdx.x >> 4;
#pragma unroll
  for (int r = 0; r < 4; r++) {
    int m = m0 + ty*4 + r;
    int n = n0 + tx*4;
#pragma unroll
    for (int j = 0; j < 4; j++) {
      float hv = g_hpre[l][m][n+j] * (1.f / (1.f + expf(-v[r][j])));
      g_h[p][l][m][n+j] = hv;
      if (l == NLY - 1)
        P.out[(size_t)m * 32768 + (size_t)t * 256 + n + j] = hv;
    }
  }
}

// ---------------------------------------------------------------------------
__global__ void seqdec_kernel(Ptrs P) {
  int idx = blockIdx.x * blockDim.x + threadIdx.x;
  int b = idx >> 7, s = idx & 127;
  const float* e = P.out + (size_t)b * 32768 + (size_t)s * 256;
  float a1[8][4], a2[8][4], a3[8][4];
#pragma unroll
  for (int g = 0; g < 8; g++)
#pragma unroll
    for (int o = 0; o < 4; o++) {
      float sum = P.sdb1[o];
#pragma unroll
      for (int m = 0; m < 32; m++) sum += e[g*32+m] * P.sdW1[o*32+m];
      a1[g][o] = sum;
    }
#pragma unroll
  for (int i = 0; i < 8; i++)
#pragma unroll
    for (int o = 0; o < 4; o++) {
      float sum = P.sdb2[o];
#pragma unroll
      for (int j = 0; j < 4; j++) {
        int f = i*4 + j;
        sum += a1[f & 7][f >> 3] * P.sdW2[o*4+j];
      }
      a2[i][o] = sum;
    }
#pragma unroll
  for (int i = 0; i < 8; i++)
#pragma unroll
    for (int o = 0; o < 4; o++) {
      float sum = P.sdb3[o];
#pragma unroll
      for (int j = 0; j < 4; j++) {
        int f = i*4 + j;
        sum += a2[f & 7][f >> 3] * P.sdW3[o*4+j];
      }
      a3[i][o] = sum;
    }
#pragma unroll
  for (int o = 0; o < 4; o++)
#pragma unroll
    for (int wv = 0; wv < 8; wv++) {
      float sum = P.sdb4[wv];
#pragma unroll
      for (int g = 0; g < 8; g++) {
        int f = o*8 + g;
        sum += a3[f >> 2][f & 3] * P.sdW4[wv*8+g];
      }
      P.out[YSEQ_OFF + (size_t)b * 4096 + (size_t)(s*8 + wv) * 4 + o] = sum;
    }
}

// ---------------------------------------------------------------------------
__global__ void onedec_kernel(Ptrs P) {
  int b = blockIdx.x;
  __shared__ float acc[10][4];
  int tid = threadIdx.x;
  if (tid < 10) {
    int s = 118 + tid;
    const float* e = P.out + (size_t)b * 32768 + (size_t)s * 256;
    float o1[8][4], o2[8][4], o3[8][4];
#pragma unroll
    for (int g = 0; g < 8; g++)
#pragma unroll
      for (int o = 0; o < 4; o++) {
        float sum = P.odb1[o];
#pragma unroll
        for (int m = 0; m < 32; m++) sum += e[g*32+m] * P.odW1[o*32+m];
        o1[g][o] = sum;
      }
#pragma unroll
    for (int i = 0; i < 8; i++)
#pragma unroll
      for (int o = 0; o < 4; o++) {
        float sum = P.odb2[o];
#pragma unroll
        for (int j = 0; j < 4; j++) {
          int f = i*4 + j;
          sum += o1[f & 7][f >> 3] * P.odW2[o*4+j];
        }
        o2[i][o] = sum;
      }
#pragma unroll
    for (int i = 0; i < 8; i++)
#pragma unroll
      for (int o = 0; o < 4; o++) {
        float sum = P.odb3[o];
#pragma unroll
        for (int j = 0; j < 4; j++) {
          int f = i*4 + j;
          sum += o2[f & 7][f >> 3] * P.odW3[o*4+j];
        }
        o3[i][o] = fmaxf(sum, 0.f);
      }
#pragma unroll
    for (int c = 0; c < 4; c++) {
      float sum = P.odb4[c];
#pragma unroll
      for (int f = 0; f < 32; f++) sum += o3[f >> 2][f & 3] * P.odW4[c*32+f];
      acc[tid][c] = 1.f / (1.f + expf(-sum));
    }
  }
  __syncthreads();
  if (tid < 4) {
    float s = 0.f;
#pragma unroll
    for (int i = 0; i < 10; i++) s += acc[i][tid];
    P.out[YONE_OFF + (size_t)b * 4 + tid] = s * 0.1f;
  }
}

// ---------------------------------------------------------------------------
extern "C" void kernel_launch(void* const* d_in, const int* in_sizes, int n_in,
                              void* d_out, int out_size) {
  (void)in_sizes; (void)n_in; (void)out_size;
  Ptrs P;
  P.x    = (const float*)d_in[0];
  P.Wih0 = (const float*)d_in[1];
  P.Wih  = (const float*)d_in[2];
  P.Whh  = (const float*)d_in[3];
  P.bih  = (const float*)d_in[4];
  P.bhh  = (const float*)d_in[5];
  P.h0   = (const float*)d_in[6];
  P.aW1  = (const float*)d_in[7];
  P.aW2  = (const float*)d_in[8];
  P.aW3  = (const float*)d_in[9];
  P.aW4  = (const float*)d_in[10];
  P.sdW1 = (const float*)d_in[11];
  P.sdb1 = (const float*)d_in[12];
  P.sdW2 = (const float*)d_in[13];
  P.sdb2 = (const float*)d_in[14];
  P.sdW3 = (const float*)d_in[15];
  P.sdb3 = (const float*)d_in[16];
  P.sdW4 = (const float*)d_in[17];
  P.sdb4 = (const float*)d_in[18];
  P.odW1 = (const float*)d_in[19];
  P.odb1 = (const float*)d_in[20];
  P.odW2 = (const float*)d_in[21];
  P.odb2 = (const float*)d_in[22];
  P.odW3 = (const float*)d_in[23];
  P.odb3 = (const float*)d_in[24];
  P.odW4 = (const float*)d_in[25];
  P.odb4 = (const float*)d_in[26];
  P.out  = (float*)d_out;

  prep_kernel<<<384, 256>>>(P);

  for (int w = 0; w < SS + NLY - 1; w++) {
    int lmin = w - (SS - 1); if (lmin < 0) lmin = 0;
    int lmax = (w < NLY - 1) ? w : NLY - 1;
    int nA = lmax - lmin + 1;
    int pp = (w + 1) & 1;
    int p  = w & 1;
    gru_gemm_kernel<<<dim3(48, nA), 256>>>(P, w, lmin, pp);
    gatesort_kernel<<<dim3(32, nA), 256>>>(P, w, lmin, pp);
    a1_kernel<<<dim3(16, nA), 256>>>(P, lmin);
    a23_kernel<<<dim3(16, nA), 256>>>(P, lmin, 2);
    a23_kernel<<<dim3(16, nA), 256>>>(P, lmin, 3);
    a4_kernel<<<dim3(16, nA), 256>>>(P, w, lmin, p);
  }

  seqdec_kernel<<<128, 256>>>(P);
  onedec_kernel<<<256, 32>>>(P);
}